// round 2
// baseline (speedup 1.0000x reference)
#include <cuda_runtime.h>
#include <math.h>

#define NB   2
#define NCAM 6
#define DIM  128
#define NH   4
#define DH   32
#define QTOK 1024
#define KTOK 1680
#define NTILE 53

__device__ float g_Qh[NB*NH*NCAM*QTOK*DH];
__device__ float g_Kh[NB*NH*NCAM*KTOK*DH];
__device__ float g_Vh[NB*NH*NCAM*KTOK*DH];
__device__ float g_A [NB*QTOK*DIM];
__device__ float g_Z [NB*QTOK*DIM];
__device__ float g_Hb[NB*QTOK*2*DIM];

// ---------- LN + 128x128 proj + head split ----------
__global__ __launch_bounds__(256) void proj_kernel(
    const float* __restrict__ in, const float* __restrict__ lng,
    const float* __restrict__ lnb, const float* __restrict__ W,
    const float* __restrict__ bias, float* __restrict__ out,
    int S, int tilesPerImg, float oscale)
{
  extern __shared__ float sm[];
  float* xs = sm;            // [128][64]
  float* mu = xs + DIM*64;
  float* rs = mu + 64;
  float* Ws = rs + 64;       // [128][128]
  const int tid = threadIdx.x;
  const int img = blockIdx.x / tilesPerImg;
  const int t0  = (blockIdx.x % tilesPerImg) * 64;
  const int ntok = min(64, S - t0);
  const int b = img / NCAM, n = img % NCAM;
  const float* base = in + (size_t)img * DIM * S + t0;

  for (int idx = tid; idx < DIM*64; idx += 256) {
    int d = idx >> 6, t = idx & 63;
    xs[idx] = (t < ntok) ? base[(size_t)d * S + t] : 0.f;
  }
  for (int idx = tid; idx < DIM*DIM; idx += 256) Ws[idx] = W[idx];
  __syncthreads();

  if (tid < 64) {
    float s = 0.f, s2 = 0.f;
    #pragma unroll 8
    for (int d = 0; d < DIM; d++) { float v = xs[d*64 + tid]; s += v; s2 += v*v; }
    float m = s * (1.f/DIM);
    float var = fmaxf(s2 * (1.f/DIM) - m*m, 0.f);
    mu[tid] = m; rs[tid] = rsqrtf(var + 1e-5f);
  }
  __syncthreads();
  for (int idx = tid; idx < DIM*64; idx += 256) {
    int d = idx >> 6, t = idx & 63;
    xs[idx] = (xs[idx] - mu[t]) * rs[t] * lng[d] + lnb[d];
  }
  __syncthreads();

  const int tk = tid & 15, jg = tid >> 4;   // 4 tokens x 8 outputs
  float acc[4][8];
  #pragma unroll
  for (int i = 0; i < 4; i++)
    #pragma unroll
    for (int jj = 0; jj < 8; jj++) acc[i][jj] = bias[jg*8 + jj];
  #pragma unroll 4
  for (int d = 0; d < DIM; d++) {
    float xv[4];
    #pragma unroll
    for (int i = 0; i < 4; i++) xv[i] = xs[d*64 + tk*4 + i];
    const float* wr = Ws + d*DIM + jg*8;
    #pragma unroll
    for (int jj = 0; jj < 8; jj++) {
      float w = wr[jj];
      #pragma unroll
      for (int i = 0; i < 4; i++) acc[i][jj] += xv[i] * w;
    }
  }
  #pragma unroll
  for (int i = 0; i < 4; i++) {
    int t = tk*4 + i;
    if (t >= ntok) continue;
    #pragma unroll
    for (int jj = 0; jj < 8; jj++) {
      int j = jg*8 + jj, h = j >> 5, dh = j & 31;
      out[(((size_t)(b*NH + h)*NCAM + n)*S + t0 + t)*DH + dh] = acc[i][jj] * oscale;
    }
  }
}

// ---------- fused multi-camera flash attention ----------
__global__ __launch_bounds__(256) void attn_kernel()
{
  extern __shared__ float sm[];
  float* q_s  = sm;                  // [6][64][33]
  float* k_sb = q_s  + NCAM*64*33;   // [2grp][2buf][1056]
  float* v_sb = k_sb + 4*1056;
  float* mrg  = v_sb + 4*1056;       // m[64], l[64], acc[64][32]
  const int tid = threadIdx.x;
  const int bh  = blockIdx.x >> 4;
  const int q0  = (blockIdx.x & 15) * 64;

  for (int idx = tid; idx < NCAM*64*32; idx += 256) {
    int c = idx >> 11, r = idx & 2047;
    int qq = r >> 5, d = r & 31;
    q_s[(c*64 + qq)*33 + d] = g_Qh[((size_t)(bh*NCAM + c)*QTOK + q0)*DH + r];
  }
  __syncthreads();

  const int w = tid >> 5, lane = tid & 31;
  const int kw = w >> 2, qw = w & 3;
  const int qr = lane >> 3, kc = lane & 7;
  const int qbase = qw * 16;
  const int gt = tid & 127;

  float acc[4][4] = {};
  float m[4], l[4];
  #pragma unroll
  for (int j = 0; j < 4; j++) { m[j] = -1e30f; l[j] = 0.f; }

  int it = 0;
  for (int tt = kw; tt < NCAM*NTILE; tt += 2, ++it) {
    int c = tt / NTILE, kt = tt - c*NTILE;
    int k0 = kt * 32;
    int kn = min(32, KTOK - k0);
    float* ks = k_sb + (kw*2 + (it & 1))*1056;
    float* vs = v_sb + (kw*2 + (it & 1))*1056;
    const size_t kb = ((size_t)(bh*NCAM + c)*KTOK + k0)*DH;
    for (int idx = gt; idx < 1024; idx += 128) {
      int kk = idx >> 5;
      bool ok = kk < kn;
      ks[kk*33 + (idx & 31)] = ok ? g_Kh[kb + idx] : 0.f;
      vs[kk*33 + (idx & 31)] = ok ? g_Vh[kb + idx] : 0.f;
    }
    asm volatile("bar.sync %0, 128;" :: "r"(kw + 1) : "memory");

    float s4[4][4] = {};
    const float* qs  = q_s + (c*64 + qbase)*33;
    const float* ksl = ks + kc*4*33;
    #pragma unroll
    for (int d = 0; d < 32; d++) {
      float kv0 = ksl[d], kv1 = ksl[33+d], kv2 = ksl[66+d], kv3 = ksl[99+d];
      #pragma unroll
      for (int j = 0; j < 4; j++) {
        float qv = qs[(qr*4 + j)*33 + d];
        s4[j][0] += qv*kv0; s4[j][1] += qv*kv1;
        s4[j][2] += qv*kv2; s4[j][3] += qv*kv3;
      }
    }
    if (kn < 32) {
      #pragma unroll
      for (int ki = 0; ki < 4; ki++)
        if (kc*4 + ki >= kn) {
          #pragma unroll
          for (int j = 0; j < 4; j++) s4[j][ki] = -1e30f;
        }
    }

    float p[4][4];
    #pragma unroll
    for (int j = 0; j < 4; j++) {
      float tmax = fmaxf(fmaxf(s4[j][0], s4[j][1]), fmaxf(s4[j][2], s4[j][3]));
      tmax = fmaxf(tmax, __shfl_xor_sync(0xffffffffu, tmax, 1));
      tmax = fmaxf(tmax, __shfl_xor_sync(0xffffffffu, tmax, 2));
      tmax = fmaxf(tmax, __shfl_xor_sync(0xffffffffu, tmax, 4));
      float mn = fmaxf(m[j], tmax);
      float corr = __expf(m[j] - mn);
      m[j] = mn;
      float ps = 0.f;
      #pragma unroll
      for (int ki = 0; ki < 4; ki++) { p[j][ki] = __expf(s4[j][ki] - mn); ps += p[j][ki]; }
      ps += __shfl_xor_sync(0xffffffffu, ps, 1);
      ps += __shfl_xor_sync(0xffffffffu, ps, 2);
      ps += __shfl_xor_sync(0xffffffffu, ps, 4);
      l[j] = l[j]*corr + ps;
      #pragma unroll
      for (int di = 0; di < 4; di++) acc[j][di] *= corr;
    }

    #pragma unroll
    for (int k = 0; k < 32; k++) {
      int src = (lane & 24) | (k >> 2);
      const float* vrow = vs + k*33 + kc*4;
      float v0 = vrow[0], v1 = vrow[1], v2 = vrow[2], v3 = vrow[3];
      #pragma unroll
      for (int j = 0; j < 4; j++) {
        float pk = __shfl_sync(0xffffffffu, p[j][k & 3], src);
        acc[j][0] += pk*v0; acc[j][1] += pk*v1;
        acc[j][2] += pk*v2; acc[j][3] += pk*v3;
      }
    }
  }

  float* mm = mrg; float* ml = mrg + 64; float* ma = mrg + 128;
  if (kw == 1) {
    #pragma unroll
    for (int j = 0; j < 4; j++) {
      int qi = qbase + qr*4 + j;
      if (kc == 0) { mm[qi] = m[j]; ml[qi] = l[j]; }
      #pragma unroll
      for (int di = 0; di < 4; di++) ma[qi*32 + kc*4 + di] = acc[j][di];
    }
  }
  __syncthreads();
  if (kw == 0) {
    int b = bh >> 2, h = bh & 3;
    #pragma unroll
    for (int j = 0; j < 4; j++) {
      int qi = qbase + qr*4 + j;
      float m1 = mm[qi], l1 = ml[qi];
      float mf = fmaxf(m[j], m1);
      float c0 = __expf(m[j] - mf), c1 = __expf(m1 - mf);
      float inv = 1.f / (l[j]*c0 + l1*c1);
      #pragma unroll
      for (int di = 0; di < 4; di++) {
        float a1 = ma[qi*32 + kc*4 + di];
        g_A[((size_t)b*QTOK + q0 + qi)*DIM + h*DH + kc*4 + di] =
            (acc[j][di]*c0 + a1*c1) * inv;
      }
    }
  }
}

// ---------- out-proj + skip + pre-LN ----------
__global__ __launch_bounds__(256) void aproj_kernel(
    const float* __restrict__ skip, const float* __restrict__ Wp,
    const float* __restrict__ bp, const float* __restrict__ pg,
    const float* __restrict__ pb)
{
  extern __shared__ float sm[];
  float* xs = sm;            // [128][64]
  float* mu = xs + 8192; float* rs = mu + 64;
  float* Ws = rs + 64;
  const int tid = threadIdx.x;
  const int tok0 = blockIdx.x * 64;
  const int b = tok0 >> 10, qb0 = tok0 & 1023;

  for (int idx = tid; idx < 8192; idx += 256) {
    int t = idx >> 7, d = idx & 127;
    xs[d*64 + t] = g_A[(size_t)(tok0 + t)*DIM + d];
  }
  for (int idx = tid; idx < DIM*DIM; idx += 256) Ws[idx] = Wp[idx];
  __syncthreads();

  const int tk = tid & 15, jg = tid >> 4;
  float acc[4][8];
  #pragma unroll
  for (int i = 0; i < 4; i++)
    #pragma unroll
    for (int jj = 0; jj < 8; jj++) acc[i][jj] = bp[jg*8 + jj];
  #pragma unroll 4
  for (int d = 0; d < DIM; d++) {
    float xv[4];
    #pragma unroll
    for (int i = 0; i < 4; i++) xv[i] = xs[d*64 + tk*4 + i];
    const float* wr = Ws + d*DIM + jg*8;
    #pragma unroll
    for (int jj = 0; jj < 8; jj++) {
      float w = wr[jj];
      #pragma unroll
      for (int i = 0; i < 4; i++) acc[i][jj] += xv[i] * w;
    }
  }
  #pragma unroll
  for (int i = 0; i < 4; i++)
    #pragma unroll
    for (int jj = 0; jj < 8; jj++)
      acc[i][jj] += skip[((size_t)b*DIM + jg*8 + jj)*QTOK + qb0 + tk*4 + i];
  __syncthreads();
  #pragma unroll
  for (int i = 0; i < 4; i++)
    #pragma unroll
    for (int jj = 0; jj < 8; jj++)
      xs[(jg*8 + jj)*64 + tk*4 + i] = acc[i][jj];
  __syncthreads();
  if (tid < 64) {
    float s = 0.f, s2 = 0.f;
    #pragma unroll 8
    for (int j = 0; j < DIM; j++) { float v = xs[j*64 + tid]; s += v; s2 += v*v; }
    float mval = s * (1.f/DIM);
    float var = fmaxf(s2 * (1.f/DIM) - mval*mval, 0.f);
    mu[tid] = mval; rs[tid] = rsqrtf(var + 1e-5f);
  }
  __syncthreads();
  for (int idx = tid; idx < 8192; idx += 256) {
    int t = idx >> 7, d = idx & 127;
    g_Z[(size_t)(tok0 + t)*DIM + d] = (xs[d*64 + t] - mu[t]) * rs[t] * pg[d] + pb[d];
  }
}

// ---------- MLP1: gelu(Z@W1+b1) ----------
__global__ __launch_bounds__(256) void mlp1_kernel(
    const float* __restrict__ W1, const float* __restrict__ b1)
{
  extern __shared__ float sm[];
  float* xs = sm;            // [128][64]
  float* Ws = xs + 8192;     // [128][256]
  const int tid = threadIdx.x;
  const int tok0 = blockIdx.x * 64;

  for (int idx = tid; idx < 8192; idx += 256) {
    int t = idx >> 7, d = idx & 127;
    xs[d*64 + t] = g_Z[(size_t)(tok0 + t)*DIM + d];
  }
  for (int idx = tid; idx < DIM*2*DIM; idx += 256) Ws[idx] = W1[idx];
  __syncthreads();

  const int tk = tid & 15, jg = tid >> 4;   // 4 tokens x 16 outputs
  float acc[4][16];
  #pragma unroll
  for (int i = 0; i < 4; i++)
    #pragma unroll
    for (int jj = 0; jj < 16; jj++) acc[i][jj] = b1[jg*16 + jj];
  #pragma unroll 2
  for (int d = 0; d < DIM; d++) {
    float xv[4];
    #pragma unroll
    for (int i = 0; i < 4; i++) xv[i] = xs[d*64 + tk*4 + i];
    const float* wr = Ws + d*2*DIM + jg*16;
    #pragma unroll
    for (int jj = 0; jj < 16; jj++) {
      float w = wr[jj];
      #pragma unroll
      for (int i = 0; i < 4; i++) acc[i][jj] += xv[i] * w;
    }
  }
  #pragma unroll
  for (int i = 0; i < 4; i++) {
    int t = tk*4 + i;
    #pragma unroll
    for (int jj = 0; jj < 16; jj++) {
      float x = acc[i][jj];
      g_Hb[(size_t)(tok0 + t)*(2*DIM) + jg*16 + jj] =
          0.5f * x * (1.f + erff(x * 0.70710678118654752f));
    }
  }
}

// ---------- MLP2 + residual + post-LN + transpose ----------
__global__ __launch_bounds__(256) void mlp2_kernel(
    const float* __restrict__ W2, const float* __restrict__ b2,
    const float* __restrict__ pg, const float* __restrict__ pb,
    float* __restrict__ out)
{
  extern __shared__ float sm[];
  float* xs = sm;              // [256][64]
  float* mu = xs + 16384; float* rs = mu + 64;
  float* Ws = rs + 64;         // [256][128]
  const int tid = threadIdx.x;
  const int tok0 = blockIdx.x * 64;
  const int b = tok0 >> 10, qb0 = tok0 & 1023;

  for (int idx = tid; idx < 16384; idx += 256) {
    int t = idx >> 8, d = idx & 255;
    xs[d*64 + t] = g_Hb[(size_t)(tok0 + t)*(2*DIM) + d];
  }
  for (int idx = tid; idx < 2*DIM*DIM; idx += 256) Ws[idx] = W2[idx];
  __syncthreads();

  const int tk = tid & 15, jg = tid >> 4;
  float acc[4][8];
  #pragma unroll
  for (int i = 0; i < 4; i++)
    #pragma unroll
    for (int jj = 0; jj < 8; jj++) acc[i][jj] = b2[jg*8 + jj];
  #pragma unroll 4
  for (int d = 0; d < 2*DIM; d++) {
    float xv[4];
    #pragma unroll
    for (int i = 0; i < 4; i++) xv[i] = xs[d*64 + tk*4 + i];
    const float* wr = Ws + d*DIM + jg*8;
    #pragma unroll
    for (int jj = 0; jj < 8; jj++) {
      float w = wr[jj];
      #pragma unroll
      for (int i = 0; i < 4; i++) acc[i][jj] += xv[i] * w;
    }
  }
  #pragma unroll
  for (int i = 0; i < 4; i++)
    #pragma unroll
    for (int jj = 0; jj < 8; jj++)
      acc[i][jj] += g_Z[(size_t)(tok0 + tk*4 + i)*DIM + jg*8 + jj];
  __syncthreads();
  #pragma unroll
  for (int i = 0; i < 4; i++)
    #pragma unroll
    for (int jj = 0; jj < 8; jj++)
      xs[(jg*8 + jj)*64 + tk*4 + i] = acc[i][jj];
  __syncthreads();
  if (tid < 64) {
    float s = 0.f, s2 = 0.f;
    #pragma unroll 8
    for (int j = 0; j < DIM; j++) { float v = xs[j*64 + tid]; s += v; s2 += v*v; }
    float mval = s * (1.f/DIM);
    float var = fmaxf(s2 * (1.f/DIM) - mval*mval, 0.f);
    mu[tid] = mval; rs[tid] = rsqrtf(var + 1e-5f);
  }
  __syncthreads();
  for (int idx = tid; idx < 8192; idx += 256) {
    int d = idx >> 6, t = idx & 63;
    out[((size_t)b*DIM + d)*QTOK + qb0 + t] =
        (xs[d*64 + t] - mu[t]) * rs[t] * pg[d] + pb[d];
  }
}

// ---------- host launcher ----------
extern "C" void kernel_launch(void* const* d_in, const int* in_sizes, int n_in,
                              void* d_out, int out_size)
{
  const float* q      = (const float*)d_in[0];
  const float* k      = (const float*)d_in[1];
  const float* v      = (const float*)d_in[2];
  const float* skip   = (const float*)d_in[3];
  const float* q_ln_g = (const float*)d_in[4];
  const float* q_ln_b = (const float*)d_in[5];
  const float* Wq     = (const float*)d_in[6];
  const float* bq     = (const float*)d_in[7];
  const float* k_ln_g = (const float*)d_in[8];
  const float* k_ln_b = (const float*)d_in[9];
  const float* Wk     = (const float*)d_in[10];
  const float* bk     = (const float*)d_in[11];
  const float* v_ln_g = (const float*)d_in[12];
  const float* v_ln_b = (const float*)d_in[13];
  const float* Wv     = (const float*)d_in[14];
  const float* bv     = (const float*)d_in[15];
  const float* Wp     = (const float*)d_in[16];
  const float* bp     = (const float*)d_in[17];
  const float* pre_g  = (const float*)d_in[18];
  const float* pre_b  = (const float*)d_in[19];
  const float* W1     = (const float*)d_in[20];
  const float* b1     = (const float*)d_in[21];
  const float* W2     = (const float*)d_in[22];
  const float* b2     = (const float*)d_in[23];
  const float* post_g = (const float*)d_in[24];
  const float* post_b = (const float*)d_in[25];
  float* out = (float*)d_out;

  float *dQh, *dKh, *dVh;
  cudaGetSymbolAddress((void**)&dQh, g_Qh);
  cudaGetSymbolAddress((void**)&dKh, g_Kh);
  cudaGetSymbolAddress((void**)&dVh, g_Vh);

  const int projSm  = (8192 + 128 + 16384) * 4;            // 98,816
  const int attnSm  = (NCAM*64*33 + 8*1056 + 64+64+2048) * 4; // 93,184
  const int mlp1Sm  = (8192 + 32768) * 4;                  // 163,840
  const int mlp2Sm  = (16384 + 128 + 32768) * 4;           // 197,120

  static bool attrSet = false;
  if (!attrSet) {
    cudaFuncSetAttribute(proj_kernel,  cudaFuncAttributeMaxDynamicSharedMemorySize, projSm);
    cudaFuncSetAttribute(attn_kernel,  cudaFuncAttributeMaxDynamicSharedMemorySize, attnSm);
    cudaFuncSetAttribute(aproj_kernel, cudaFuncAttributeMaxDynamicSharedMemorySize, projSm);
    cudaFuncSetAttribute(mlp1_kernel,  cudaFuncAttributeMaxDynamicSharedMemorySize, mlp1Sm);
    cudaFuncSetAttribute(mlp2_kernel,  cudaFuncAttributeMaxDynamicSharedMemorySize, mlp2Sm);
    attrSet = true;
  }

  const float qscale = rsqrtf((float)DH);
  // q: S=1024 -> 16 tiles/img; k,v: S=1680 -> 27 tiles/img (ceil(1680/64)=27)
  proj_kernel<<<NB*NCAM*16, 256, projSm>>>(q, q_ln_g, q_ln_b, Wq, bq, dQh, QTOK, 16, qscale);
  proj_kernel<<<NB*NCAM*27, 256, projSm>>>(k, k_ln_g, k_ln_b, Wk, bk, dKh, KTOK, 27, 1.f);
  proj_kernel<<<NB*NCAM*27, 256, projSm>>>(v, v_ln_g, v_ln_b, Wv, bv, dVh, KTOK, 27, 1.f);
  attn_kernel<<<NB*NH*16, 256, attnSm>>>();
  aproj_kernel<<<NB*QTOK/64, 256, projSm>>>(skip, Wp, bp, pre_g, pre_b);
  mlp1_kernel<<<NB*QTOK/64, 256, mlp1Sm>>>(W1, b1);
  mlp2_kernel<<<NB*QTOK/64, 256, mlp2Sm>>>(W2, b2, post_g, post_b, out);
  (void)in_sizes; (void)n_in; (void)out_size;
}

// round 12
// speedup vs baseline: 1.0219x; 1.0219x over previous
#include <cuda_runtime.h>
#include <math.h>

#define NB   2
#define NCAM 6
#define DIM  128
#define NH   4
#define DH   32
#define QTOK 1024
#define KTOK 1680
#define NTILE 53

typedef unsigned long long u64;

__device__ float g_Qh[NB*NH*NCAM*QTOK*DH];
__device__ float g_Kh[NB*NH*NCAM*KTOK*DH];
__device__ float g_VhT[NB*NH*NCAM*DH*KTOK];   // transposed: [bh][cam][dh][k]
__device__ float g_A [NB*QTOK*DIM];
__device__ float g_Z [NB*QTOK*DIM];
__device__ float g_Hb[NB*QTOK*2*DIM];

#define FMA2(d,a,b,c) asm("fma.rn.f32x2 %0, %1, %2, %3;" : "=l"(d) : "l"(a), "l"(b), "l"(c))
#define MUL2(d,a,b)   asm("mul.rn.f32x2 %0, %1, %2;"     : "=l"(d) : "l"(a), "l"(b))

__device__ __forceinline__ u64 pk2(float x, float y) {
  u64 r; asm("mov.b64 %0, {%1, %2};" : "=l"(r) : "f"(x), "f"(y)); return r;
}
__device__ __forceinline__ float2 unpk(u64 v) {
  float2 r; asm("mov.b64 {%0, %1}, %2;" : "=f"(r.x), "=f"(r.y) : "l"(v)); return r;
}

// ---------- LN + 128x128 proj + head split (optional transposed output) ----------
__global__ __launch_bounds__(256) void proj_kernel(
    const float* __restrict__ in, const float* __restrict__ lng,
    const float* __restrict__ lnb, const float* __restrict__ W,
    const float* __restrict__ bias, float* __restrict__ out,
    int S, int tilesPerImg, float oscale, int transV)
{
  extern __shared__ float sm[];
  float* xs = sm;            // [128][64]
  float* mu = xs + DIM*64;
  float* rs = mu + 64;
  float* Ws = rs + 64;       // [128][128]
  const int tid = threadIdx.x;
  const int img = blockIdx.x / tilesPerImg;
  const int t0  = (blockIdx.x % tilesPerImg) * 64;
  const int ntok = min(64, S - t0);
  const int b = img / NCAM, n = img % NCAM;
  const float* base = in + (size_t)img * DIM * S + t0;

  for (int idx = tid; idx < DIM*64; idx += 256) {
    int d = idx >> 6, t = idx & 63;
    xs[idx] = (t < ntok) ? base[(size_t)d * S + t] : 0.f;
  }
  for (int idx = tid; idx < DIM*DIM; idx += 256) Ws[idx] = W[idx];
  __syncthreads();

  if (tid < 64) {
    float s = 0.f, s2 = 0.f;
    #pragma unroll 8
    for (int d = 0; d < DIM; d++) { float v = xs[d*64 + tid]; s += v; s2 += v*v; }
    float m = s * (1.f/DIM);
    float var = fmaxf(s2 * (1.f/DIM) - m*m, 0.f);
    mu[tid] = m; rs[tid] = rsqrtf(var + 1e-5f);
  }
  __syncthreads();
  for (int idx = tid; idx < DIM*64; idx += 256) {
    int d = idx >> 6, t = idx & 63;
    xs[idx] = (xs[idx] - mu[t]) * rs[t] * lng[d] + lnb[d];
  }
  __syncthreads();

  const int tk = tid & 15, jg = tid >> 4;   // 4 tokens x 8 outputs
  float acc[4][8];
  #pragma unroll
  for (int i = 0; i < 4; i++)
    #pragma unroll
    for (int jj = 0; jj < 8; jj++) acc[i][jj] = bias[jg*8 + jj];
  #pragma unroll 4
  for (int d = 0; d < DIM; d++) {
    float xv[4];
    #pragma unroll
    for (int i = 0; i < 4; i++) xv[i] = xs[d*64 + tk*4 + i];
    const float* wr = Ws + d*DIM + jg*8;
    #pragma unroll
    for (int jj = 0; jj < 8; jj++) {
      float w = wr[jj];
      #pragma unroll
      for (int i = 0; i < 4; i++) acc[i][jj] += xv[i] * w;
    }
  }
  if (!transV) {
    #pragma unroll
    for (int i = 0; i < 4; i++) {
      int t = tk*4 + i;
      if (t >= ntok) continue;
      #pragma unroll
      for (int jj = 0; jj < 8; jj++) {
        int j = jg*8 + jj, h = j >> 5, dh = j & 31;
        out[(((size_t)(b*NH + h)*NCAM + n)*S + t0 + t)*DH + dh] = acc[i][jj] * oscale;
      }
    }
  } else {
    if (tk*4 < ntok) {
      #pragma unroll
      for (int jj = 0; jj < 8; jj++) {
        int j = jg*8 + jj, h = j >> 5, dh = j & 31;
        float4 vv = make_float4(acc[0][jj], acc[1][jj], acc[2][jj], acc[3][jj]);
        *(float4*)&out[(((size_t)(b*NH + h)*NCAM + n)*DH + dh)*S + t0 + tk*4] = vv;
      }
    }
  }
}

// ---------- fused multi-camera flash attention v2 ----------
// grid = NB*NH*32 (32-query tiles), 256 threads = 8 warps.
// 4 key-split groups (kw) x 2 query warps (qw, 16q each). Lane tile 4q x 4k.
// f32x2 packed FMA throughout; P staged through per-warp smem; V transposed.
__global__ void __launch_bounds__(256, 2) attn_kernel()
{
  extern __shared__ float sm[];
  float* q_s  = sm;              // 6*32*32, swizzled + row-permuted
  float* k_s  = q_s + 6144;      // 4 grp x 2 buf x 32x32, swizzled
  float* vT_s = k_s + 8192;      // 4 grp x 2 buf x 32(d)x32(k), swizzled
  float* p_s  = vT_s + 8192;     // 4 grp x 32(q) x 32(k), swizzled
  float* mrg  = k_s;             // overlay after final __syncthreads

  const int tid = threadIdx.x;
  const int bh  = blockIdx.x >> 5;
  const int q0  = (blockIdx.x & 31) * 32;

  // stage Q: 1536 float4
  for (int i = tid; i < 1536; i += 256) {
    int c = i >> 8;
    int r = i & 255;
    int q = r >> 3, gl = r & 7;
    float4 val = *(const float4*)&g_Qh[(((size_t)bh*NCAM + c)*QTOK + q0 + q)*DH + gl*4];
    int p = (q & 16) | ((q & 3) << 2) | ((q >> 2) & 3);   // row permutation
    *(float4*)&q_s[c*1024 + p*32 + ((gl ^ (p & 7)) << 2)] = val;
  }
  __syncthreads();

  const int lane = tid & 31;
  const int kw = tid >> 6, qw = (tid >> 5) & 1;
  const int qr = lane >> 3, kc = lane & 7;
  const int qbase = qw << 4;
  const int gt = tid & 63;

  float* ksb = k_s  + kw*2048;
  float* vsb = vT_s + kw*2048;
  float* psw = p_s  + kw*1024;

  u64 acc2[4][4];
  float m[4], l[4];
  #pragma unroll
  for (int j = 0; j < 4; j++) {
    m[j] = -1e30f; l[j] = 0.f;
    #pragma unroll
    for (int di = 0; di < 4; di++) acc2[j][di] = 0ull;
  }

  const int ntiles = (NCAM*NTILE - kw + 3) >> 2;
  const int skk = gt >> 1, sh2 = gt & 1;

  auto stage = [&](int tt, int buf) {
    int c = tt / NTILE, kt = tt - c*NTILE;
    int k0 = kt << 5;
    int kn = min(32, KTOK - k0);
    float* ks = ksb + buf*1024;
    float* vs = vsb + buf*1024;
    const float* ksrc = &g_Kh[(((size_t)bh*NCAM + c)*KTOK + k0 + skk)*DH + sh2*16];
    #pragma unroll
    for (int g = 0; g < 4; g++) {
      float4 val = (skk < kn) ? *(const float4*)(ksrc + g*4) : make_float4(0.f,0.f,0.f,0.f);
      int gl = sh2*4 + g;
      *(float4*)&ks[skk*32 + ((gl ^ (skk >> 2)) << 2)] = val;
    }
    const float* vsrc = &g_VhT[(((size_t)bh*NCAM + c)*DH + skk)*KTOK + k0 + sh2*16];
    #pragma unroll
    for (int g = 0; g < 4; g++) {
      int kloc = sh2*16 + g*4;
      float4 val = (kloc < kn) ? *(const float4*)(vsrc + g*4) : make_float4(0.f,0.f,0.f,0.f);
      *(float4*)&vs[skk*32 + (((kloc >> 2) ^ ((skk >> 2) & 7)) << 2)] = val;
    }
  };

  stage(kw, 0);
  asm volatile("bar.sync %0, 64;" :: "r"(kw + 1) : "memory");

  for (int it = 0; it < ntiles; ++it) {
    const int tt = kw + (it << 2);
    const int c = tt / NTILE;
    const int k0 = (tt - c*NTILE) << 5;
    const int kn = min(32, KTOK - k0);
    const int buf = it & 1;
    const float* ks = ksb + buf*1024;
    const float* vs = vsb + buf*1024;
    const float* qs = q_s + c*1024;

    // ---- logits (d-paired f32x2) ----
    u64 s4p[4][4];
    #pragma unroll
    for (int j = 0; j < 4; j++)
      #pragma unroll
      for (int ki = 0; ki < 4; ki++) s4p[j][ki] = 0ull;

    #pragma unroll
    for (int D4 = 0; D4 < 8; D4++) {
      u64 qp0[4], qp1[4];
      #pragma unroll
      for (int j = 0; j < 4; j++) {
        int pr = qbase + (j << 2) + qr;
        ulonglong2 t = *(const ulonglong2*)&qs[pr*32 + ((D4 ^ (pr & 7)) << 2)];
        qp0[j] = t.x; qp1[j] = t.y;
      }
      #pragma unroll
      for (int ki = 0; ki < 4; ki++) {
        int kk = (kc << 2) + ki;
        ulonglong2 t = *(const ulonglong2*)&ks[kk*32 + ((D4 ^ kc) << 2)];
        #pragma unroll
        for (int j = 0; j < 4; j++) {
          FMA2(s4p[j][ki], qp0[j], t.x, s4p[j][ki]);
          FMA2(s4p[j][ki], qp1[j], t.y, s4p[j][ki]);
        }
      }
    }
    float s4[4][4];
    #pragma unroll
    for (int j = 0; j < 4; j++)
      #pragma unroll
      for (int ki = 0; ki < 4; ki++) {
        float2 u = unpk(s4p[j][ki]);
        s4[j][ki] = u.x + u.y;
      }
    if (kn < 32) {
      #pragma unroll
      for (int ki = 0; ki < 4; ki++)
        if ((kc << 2) + ki >= kn) {
          #pragma unroll
          for (int j = 0; j < 4; j++) s4[j][ki] = -1e30f;
        }
    }

    // ---- online softmax ----
    float p[4][4];
    #pragma unroll
    for (int j = 0; j < 4; j++) {
      float tmax = fmaxf(fmaxf(s4[j][0], s4[j][1]), fmaxf(s4[j][2], s4[j][3]));
      tmax = fmaxf(tmax, __shfl_xor_sync(0xffffffffu, tmax, 1));
      tmax = fmaxf(tmax, __shfl_xor_sync(0xffffffffu, tmax, 2));
      tmax = fmaxf(tmax, __shfl_xor_sync(0xffffffffu, tmax, 4));
      float mn = fmaxf(m[j], tmax);
      float corr = __expf(m[j] - mn);
      m[j] = mn;
      float ps = 0.f;
      #pragma unroll
      for (int ki = 0; ki < 4; ki++) { p[j][ki] = __expf(s4[j][ki] - mn); ps += p[j][ki]; }
      ps += __shfl_xor_sync(0xffffffffu, ps, 1);
      ps += __shfl_xor_sync(0xffffffffu, ps, 2);
      ps += __shfl_xor_sync(0xffffffffu, ps, 4);
      l[j] = l[j]*corr + ps;
      u64 cp = pk2(corr, corr);
      #pragma unroll
      for (int di = 0; di < 4; di++) MUL2(acc2[j][di], acc2[j][di], cp);
    }

    // ---- stage P to per-warp smem ----
    #pragma unroll
    for (int j = 0; j < 4; j++) {
      int q = qbase + (qr << 2) + j;
      int pg = kc ^ ((q >> 2) & 7);
      *(float4*)&psw[q*32 + (pg << 2)] = make_float4(p[j][0], p[j][1], p[j][2], p[j][3]);
    }
    __syncwarp();

    // ---- PV (k-paired f32x2, V transposed) ----
    #pragma unroll
    for (int K4 = 0; K4 < 8; K4++) {
      u64 pp0[4], pp1[4];
      #pragma unroll
      for (int j = 0; j < 4; j++) {
        int q = qbase + (qr << 2) + j;
        ulonglong2 t = *(const ulonglong2*)&psw[q*32 + ((K4 ^ ((q >> 2) & 7)) << 2)];
        pp0[j] = t.x; pp1[j] = t.y;
      }
      #pragma unroll
      for (int di = 0; di < 4; di++) {
        int d = (kc << 2) + di;
        ulonglong2 t = *(const ulonglong2*)&vs[d*32 + ((K4 ^ kc) << 2)];
        #pragma unroll
        for (int j = 0; j < 4; j++) {
          FMA2(acc2[j][di], pp0[j], t.x, acc2[j][di]);
          FMA2(acc2[j][di], pp1[j], t.y, acc2[j][di]);
        }
      }
    }

    if (it + 1 < ntiles) stage(kw + ((it + 1) << 2), buf ^ 1);
    asm volatile("bar.sync %0, 64;" :: "r"(kw + 1) : "memory");
  }

  // collapse k-parity pairs
  float accf[4][4];
  #pragma unroll
  for (int j = 0; j < 4; j++)
    #pragma unroll
    for (int di = 0; di < 4; di++) {
      float2 u = unpk(acc2[j][di]);
      accf[j][di] = u.x + u.y;
    }

  __syncthreads();   // all groups done with k_s -> overlay merge region
  float* mm = mrg;          // [3][32]
  float* ml = mrg + 96;     // [3][32]
  float* ma = mrg + 192;    // [3][32][32]
  if (kw != 0) {
    int g = kw - 1;
    #pragma unroll
    for (int j = 0; j < 4; j++) {
      int qi = qbase + (qr << 2) + j;
      if (kc == 0) { mm[g*32 + qi] = m[j]; ml[g*32 + qi] = l[j]; }
      #pragma unroll
      for (int di = 0; di < 4; di++)
        ma[(g*32 + qi)*32 + (kc << 2) + di] = accf[j][di];
    }
  }
  __syncthreads();
  if (kw == 0) {
    int b = bh >> 2, h = bh & 3;
    #pragma unroll
    for (int j = 0; j < 4; j++) {
      int qi = qbase + (qr << 2) + j;
      float mf = m[j];
      #pragma unroll
      for (int g = 0; g < 3; g++) mf = fmaxf(mf, mm[g*32 + qi]);
      float c0 = __expf(m[j] - mf);
      float li = l[j] * c0;
      float o[4];
      #pragma unroll
      for (int di = 0; di < 4; di++) o[di] = accf[j][di] * c0;
      #pragma unroll
      for (int g = 0; g < 3; g++) {
        float cg = __expf(mm[g*32 + qi] - mf);
        li += ml[g*32 + qi] * cg;
        #pragma unroll
        for (int di = 0; di < 4; di++)
          o[di] += ma[(g*32 + qi)*32 + (kc << 2) + di] * cg;
      }
      float inv = 1.f / li;
      #pragma unroll
      for (int di = 0; di < 4; di++)
        g_A[((size_t)b*QTOK + q0 + qi)*DIM + h*DH + (kc << 2) + di] = o[di] * inv;
    }
  }
}

// ---------- out-proj + skip + pre-LN ----------
__global__ __launch_bounds__(256) void aproj_kernel(
    const float* __restrict__ skip, const float* __restrict__ Wp,
    const float* __restrict__ bp, const float* __restrict__ pg,
    const float* __restrict__ pb)
{
  extern __shared__ float sm[];
  float* xs = sm;
  float* mu = xs + 8192; float* rs = mu + 64;
  float* Ws = rs + 64;
  const int tid = threadIdx.x;
  const int tok0 = blockIdx.x * 64;
  const int b = tok0 >> 10, qb0 = tok0 & 1023;

  for (int idx = tid; idx < 8192; idx += 256) {
    int t = idx >> 7, d = idx & 127;
    xs[d*64 + t] = g_A[(size_t)(tok0 + t)*DIM + d];
  }
  for (int idx = tid; idx < DIM*DIM; idx += 256) Ws[idx] = Wp[idx];
  __syncthreads();

  const int tk = tid & 15, jg = tid >> 4;
  float acc[4][8];
  #pragma unroll
  for (int i = 0; i < 4; i++)
    #pragma unroll
    for (int jj = 0; jj < 8; jj++) acc[i][jj] = bp[jg*8 + jj];
  #pragma unroll 4
  for (int d = 0; d < DIM; d++) {
    float xv[4];
    #pragma unroll
    for (int i = 0; i < 4; i++) xv[i] = xs[d*64 + tk*4 + i];
    const float* wr = Ws + d*DIM + jg*8;
    #pragma unroll
    for (int jj = 0; jj < 8; jj++) {
      float w = wr[jj];
      #pragma unroll
      for (int i = 0; i < 4; i++) acc[i][jj] += xv[i] * w;
    }
  }
  #pragma unroll
  for (int i = 0; i < 4; i++)
    #pragma unroll
    for (int jj = 0; jj < 8; jj++)
      acc[i][jj] += skip[((size_t)b*DIM + jg*8 + jj)*QTOK + qb0 + tk*4 + i];
  __syncthreads();
  #pragma unroll
  for (int i = 0; i < 4; i++)
    #pragma unroll
    for (int jj = 0; jj < 8; jj++)
      xs[(jg*8 + jj)*64 + tk*4 + i] = acc[i][jj];
  __syncthreads();
  if (tid < 64) {
    float s = 0.f, s2 = 0.f;
    #pragma unroll 8
    for (int j = 0; j < DIM; j++) { float v = xs[j*64 + tid]; s += v; s2 += v*v; }
    float mval = s * (1.f/DIM);
    float var = fmaxf(s2 * (1.f/DIM) - mval*mval, 0.f);
    mu[tid] = mval; rs[tid] = rsqrtf(var + 1e-5f);
  }
  __syncthreads();
  for (int idx = tid; idx < 8192; idx += 256) {
    int t = idx >> 7, d = idx & 127;
    g_Z[(size_t)(tok0 + t)*DIM + d] = (xs[d*64 + t] - mu[t]) * rs[t] * pg[d] + pb[d];
  }
}

// ---------- MLP1: gelu(Z@W1+b1) ----------
__global__ __launch_bounds__(256) void mlp1_kernel(
    const float* __restrict__ W1, const float* __restrict__ b1)
{
  extern __shared__ float sm[];
  float* xs = sm;
  float* Ws = xs + 8192;
  const int tid = threadIdx.x;
  const int tok0 = blockIdx.x * 64;

  for (int idx = tid; idx < 8192; idx += 256) {
    int t = idx >> 7, d = idx & 127;
    xs[d*64 + t] = g_Z[(size_t)(tok0 + t)*DIM + d];
  }
  for (int idx = tid; idx < DIM*2*DIM; idx += 256) Ws[idx] = W1[idx];
  __syncthreads();

  const int tk = tid & 15, jg = tid >> 4;
  float acc[4][16];
  #pragma unroll
  for (int i = 0; i < 4; i++)
    #pragma unroll
    for (int jj = 0; jj < 16; jj++) acc[i][jj] = b1[jg*16 + jj];
  #pragma unroll 2
  for (int d = 0; d < DIM; d++) {
    float xv[4];
    #pragma unroll
    for (int i = 0; i < 4; i++) xv[i] = xs[d*64 + tk*4 + i];
    const float* wr = Ws + d*2*DIM + jg*16;
    #pragma unroll
    for (int jj = 0; jj < 16; jj++) {
      float w = wr[jj];
      #pragma unroll
      for (int i = 0; i < 4; i++) acc[i][jj] += xv[i] * w;
    }
  }
  #pragma unroll
  for (int i = 0; i < 4; i++) {
    int t = tk*4 + i;
    #pragma unroll
    for (int jj = 0; jj < 16; jj++) {
      float x = acc[i][jj];
      g_Hb[(size_t)(tok0 + t)*(2*DIM) + jg*16 + jj] =
          0.5f * x * (1.f + erff(x * 0.70710678118654752f));
    }
  }
}

// ---------- MLP2 + residual + post-LN + transpose ----------
__global__ __launch_bounds__(256) void mlp2_kernel(
    const float* __restrict__ W2, const float* __restrict__ b2,
    const float* __restrict__ pg, const float* __restrict__ pb,
    float* __restrict__ out)
{
  extern __shared__ float sm[];
  float* xs = sm;
  float* mu = xs + 16384; float* rs = mu + 64;
  float* Ws = rs + 64;
  const int tid = threadIdx.x;
  const int tok0 = blockIdx.x * 64;
  const int b = tok0 >> 10, qb0 = tok0 & 1023;

  for (int idx = tid; idx < 16384; idx += 256) {
    int t = idx >> 8, d = idx & 255;
    xs[d*64 + t] = g_Hb[(size_t)(tok0 + t)*(2*DIM) + d];
  }
  for (int idx = tid; idx < 2*DIM*DIM; idx += 256) Ws[idx] = W2[idx];
  __syncthreads();

  const int tk = tid & 15, jg = tid >> 4;
  float acc[4][8];
  #pragma unroll
  for (int i = 0; i < 4; i++)
    #pragma unroll
    for (int jj = 0; jj < 8; jj++) acc[i][jj] = b2[jg*8 + jj];
  #pragma unroll 4
  for (int d = 0; d < 2*DIM; d++) {
    float xv[4];
    #pragma unroll
    for (int i = 0; i < 4; i++) xv[i] = xs[d*64 + tk*4 + i];
    const float* wr = Ws + d*DIM + jg*8;
    #pragma unroll
    for (int jj = 0; jj < 8; jj++) {
      float w = wr[jj];
      #pragma unroll
      for (int i = 0; i < 4; i++) acc[i][jj] += xv[i] * w;
    }
  }
  #pragma unroll
  for (int i = 0; i < 4; i++)
    #pragma unroll
    for (int jj = 0; jj < 8; jj++)
      acc[i][jj] += g_Z[(size_t)(tok0 + tk*4 + i)*DIM + jg*8 + jj];
  __syncthreads();
  #pragma unroll
  for (int i = 0; i < 4; i++)
    #pragma unroll
    for (int jj = 0; jj < 8; jj++)
      xs[(jg*8 + jj)*64 + tk*4 + i] = acc[i][jj];
  __syncthreads();
  if (tid < 64) {
    float s = 0.f, s2 = 0.f;
    #pragma unroll 8
    for (int j = 0; j < DIM; j++) { float v = xs[j*64 + tid]; s += v; s2 += v*v; }
    float mval = s * (1.f/DIM);
    float var = fmaxf(s2 * (1.f/DIM) - mval*mval, 0.f);
    mu[tid] = mval; rs[tid] = rsqrtf(var + 1e-5f);
  }
  __syncthreads();
  for (int idx = tid; idx < 8192; idx += 256) {
    int d = idx >> 6, t = idx & 63;
    out[((size_t)b*DIM + d)*QTOK + qb0 + t] =
        (xs[d*64 + t] - mu[t]) * rs[t] * pg[d] + pb[d];
  }
}

// ---------- host launcher ----------
extern "C" void kernel_launch(void* const* d_in, const int* in_sizes, int n_in,
                              void* d_out, int out_size)
{
  const float* q      = (const float*)d_in[0];
  const float* k      = (const float*)d_in[1];
  const float* v      = (const float*)d_in[2];
  const float* skip   = (const float*)d_in[3];
  const float* q_ln_g = (const float*)d_in[4];
  const float* q_ln_b = (const float*)d_in[5];
  const float* Wq     = (const float*)d_in[6];
  const float* bq     = (const float*)d_in[7];
  const float* k_ln_g = (const float*)d_in[8];
  const float* k_ln_b = (const float*)d_in[9];
  const float* Wk     = (const float*)d_in[10];
  const float* bk     = (const float*)d_in[11];
  const float* v_ln_g = (const float*)d_in[12];
  const float* v_ln_b = (const float*)d_in[13];
  const float* Wv     = (const float*)d_in[14];
  const float* bv     = (const float*)d_in[15];
  const float* Wp     = (const float*)d_in[16];
  const float* bp     = (const float*)d_in[17];
  const float* pre_g  = (const float*)d_in[18];
  const float* pre_b  = (const float*)d_in[19];
  const float* W1     = (const float*)d_in[20];
  const float* b1     = (const float*)d_in[21];
  const float* W2     = (const float*)d_in[22];
  const float* b2     = (const float*)d_in[23];
  const float* post_g = (const float*)d_in[24];
  const float* post_b = (const float*)d_in[25];
  float* out = (float*)d_out;

  float *dQh, *dKh, *dVhT;
  cudaGetSymbolAddress((void**)&dQh, g_Qh);
  cudaGetSymbolAddress((void**)&dKh, g_Kh);
  cudaGetSymbolAddress((void**)&dVhT, g_VhT);

  const int projSm  = (8192 + 128 + 16384) * 4;   // 98,816
  const int attnSm  = (6144 + 8192 + 8192 + 4096) * 4;  // 106,496
  const int mlp1Sm  = (8192 + 32768) * 4;         // 163,840
  const int mlp2Sm  = (16384 + 128 + 32768) * 4;  // 197,120

  static bool attrSet = false;
  if (!attrSet) {
    cudaFuncSetAttribute(proj_kernel,  cudaFuncAttributeMaxDynamicSharedMemorySize, projSm);
    cudaFuncSetAttribute(attn_kernel,  cudaFuncAttributeMaxDynamicSharedMemorySize, attnSm);
    cudaFuncSetAttribute(aproj_kernel, cudaFuncAttributeMaxDynamicSharedMemorySize, projSm);
    cudaFuncSetAttribute(mlp1_kernel,  cudaFuncAttributeMaxDynamicSharedMemorySize, mlp1Sm);
    cudaFuncSetAttribute(mlp2_kernel,  cudaFuncAttributeMaxDynamicSharedMemorySize, mlp2Sm);
    attrSet = true;
  }

  const float qscale = rsqrtf((float)DH);
  proj_kernel<<<NB*NCAM*16, 256, projSm>>>(q, q_ln_g, q_ln_b, Wq, bq, dQh, QTOK, 16, qscale, 0);
  proj_kernel<<<NB*NCAM*27, 256, projSm>>>(k, k_ln_g, k_ln_b, Wk, bk, dKh, KTOK, 27, 1.f, 0);
  proj_kernel<<<NB*NCAM*27, 256, projSm>>>(v, v_ln_g, v_ln_b, Wv, bv, dVhT, KTOK, 27, 1.f, 1);
  attn_kernel<<<NB*NH*32, 256, attnSm>>>();
  aproj_kernel<<<NB*QTOK/64, 256, projSm>>>(skip, Wp, bp, pre_g, pre_b);
  mlp1_kernel<<<NB*QTOK/64, 256, mlp1Sm>>>(W1, b1);
  mlp2_kernel<<<NB*QTOK/64, 256, mlp2Sm>>>(W2, b2, post_g, post_b, out);
  (void)in_sizes; (void)n_in; (void)out_size;
}

// round 16
// speedup vs baseline: 1.3714x; 1.3421x over previous
#include <cuda_runtime.h>
#include <cuda_bf16.h>
#include <math.h>

#define NB   2
#define NCAM 6
#define DIM  128
#define NH   4
#define DH   32
#define QTOK 1024
#define KTOK 1680
#define TPC  14
#define NTT  (NCAM*TPC)

typedef unsigned long long u64;
typedef unsigned int u32;

__device__ float g_Qh[NB*NH*NCAM*QTOK*DH];
__device__ float g_Kh[NB*NH*NCAM*KTOK*DH];
__device__ float g_Vh[NB*NH*NCAM*KTOK*DH];
__device__ float g_A [NB*QTOK*DIM];
__device__ float g_Z [NB*QTOK*DIM];
__device__ float g_Hb[NB*QTOK*2*DIM];
// padded bf16 hi/lo planes (80B row pitch)
__device__ unsigned char g_QA[(size_t)NB*NH*NCAM*2*1024*80];
__device__ unsigned char g_KB[(size_t)NB*NH*NCAM*TPC*2*128*80];
__device__ unsigned char g_VB[(size_t)NB*NH*NCAM*TPC*2*128*80];

static __device__ __forceinline__ u32 smem_u32(const void* p) {
  u32 a; asm("{ .reg .u64 t; cvta.to.shared.u64 t, %1; cvt.u32.u64 %0, t; }" : "=r"(a) : "l"(p));
  return a;
}
static __device__ __forceinline__ void mma16816(float* c, u32 a0,u32 a1,u32 a2,u32 a3, u32 b0,u32 b1) {
  asm volatile("mma.sync.aligned.m16n8k16.row.col.f32.bf16.bf16.f32 "
    "{%0,%1,%2,%3}, {%4,%5,%6,%7}, {%8,%9}, {%0,%1,%2,%3};"
    : "+f"(c[0]), "+f"(c[1]), "+f"(c[2]), "+f"(c[3])
    : "r"(a0),"r"(a1),"r"(a2),"r"(a3), "r"(b0),"r"(b1));
}
static __device__ __forceinline__ void ldsm4(u32 addr, u32& r0,u32& r1,u32& r2,u32& r3) {
  asm volatile("ldmatrix.sync.aligned.m8n8.x4.shared.b16 {%0,%1,%2,%3}, [%4];"
    : "=r"(r0),"=r"(r1),"=r"(r2),"=r"(r3) : "r"(addr));
}
static __device__ __forceinline__ void ldsm4t(u32 addr, u32& r0,u32& r1,u32& r2,u32& r3) {
  asm volatile("ldmatrix.sync.aligned.m8n8.x4.trans.shared.b16 {%0,%1,%2,%3}, [%4];"
    : "=r"(r0),"=r"(r1),"=r"(r2),"=r"(r3) : "r"(addr));
}
static __device__ __forceinline__ u32 pkbf(float lo, float hi) {
  u32 r; asm("cvt.rn.bf16x2.f32 %0, %1, %2;" : "=r"(r) : "f"(hi), "f"(lo));
  return r;
}

// 8 floats -> hi 16B + lo 16B
static __device__ __forceinline__ void cvt8(const float* x, uint4* hi, uint4* lo) {
  u32 h[4], l[4];
  #pragma unroll
  for (int p = 0; p < 4; p++) {
    float a = x[2*p], b = x[2*p+1];
    u32 hp = pkbf(a, b);
    float ra = a - __uint_as_float(hp << 16);
    float rb = b - __uint_as_float(hp & 0xffff0000u);
    h[p] = hp;
    l[p] = pkbf(ra, rb);
  }
  *hi = make_uint4(h[0], h[1], h[2], h[3]);
  *lo = make_uint4(l[0], l[1], l[2], l[3]);
}

// ---------- LN + 128x128 proj + head split ----------
__global__ __launch_bounds__(256) void proj_kernel(
    const float* __restrict__ in, const float* __restrict__ lng,
    const float* __restrict__ lnb, const float* __restrict__ W,
    const float* __restrict__ bias, float* __restrict__ out,
    int S, int tilesPerImg, float oscale)
{
  extern __shared__ float sm[];
  float* xs = sm;
  float* mu = xs + DIM*64;
  float* rs = mu + 64;
  float* Ws = rs + 64;
  const int tid = threadIdx.x;
  const int img = blockIdx.x / tilesPerImg;
  const int t0  = (blockIdx.x % tilesPerImg) * 64;
  const int ntok = min(64, S - t0);
  const int b = img / NCAM, n = img % NCAM;
  const float* base = in + (size_t)img * DIM * S + t0;

  for (int idx = tid; idx < DIM*64; idx += 256) {
    int d = idx >> 6, t = idx & 63;
    xs[idx] = (t < ntok) ? base[(size_t)d * S + t] : 0.f;
  }
  for (int idx = tid; idx < DIM*DIM; idx += 256) Ws[idx] = W[idx];
  __syncthreads();

  if (tid < 64) {
    float s = 0.f, s2 = 0.f;
    #pragma unroll 8
    for (int d = 0; d < DIM; d++) { float v = xs[d*64 + tid]; s += v; s2 += v*v; }
    float m = s * (1.f/DIM);
    float var = fmaxf(s2 * (1.f/DIM) - m*m, 0.f);
    mu[tid] = m; rs[tid] = rsqrtf(var + 1e-5f);
  }
  __syncthreads();
  for (int idx = tid; idx < DIM*64; idx += 256) {
    int d = idx >> 6, t = idx & 63;
    xs[idx] = (xs[idx] - mu[t]) * rs[t] * lng[d] + lnb[d];
  }
  __syncthreads();

  const int tk = tid & 15, jg = tid >> 4;
  float acc[4][8];
  #pragma unroll
  for (int i = 0; i < 4; i++)
    #pragma unroll
    for (int jj = 0; jj < 8; jj++) acc[i][jj] = bias[jg*8 + jj];
  #pragma unroll 4
  for (int d = 0; d < DIM; d++) {
    float xv[4];
    #pragma unroll
    for (int i = 0; i < 4; i++) xv[i] = xs[d*64 + tk*4 + i];
    const float* wr = Ws + d*DIM + jg*8;
    #pragma unroll
    for (int jj = 0; jj < 8; jj++) {
      float w = wr[jj];
      #pragma unroll
      for (int i = 0; i < 4; i++) acc[i][jj] += xv[i] * w;
    }
  }
  #pragma unroll
  for (int i = 0; i < 4; i++) {
    int t = tk*4 + i;
    if (t >= ntok) continue;
    #pragma unroll
    for (int jj = 0; jj < 8; jj++) {
      int j = jg*8 + jj, h = j >> 5, dh = j & 31;
      out[(((size_t)(b*NH + h)*NCAM + n)*S + t0 + t)*DH + dh] = acc[i][jj] * oscale;
    }
  }
}

// ---------- conv to padded hi/lo bf16 planes ----------
__global__ __launch_bounds__(256) void convQ_kernel()
{
  int bc = blockIdx.x >> 2, rp = blockIdx.x & 3;
  int row = rp*256 + threadIdx.x;
  const float* src = &g_Qh[((size_t)bc*QTOK + row)*DH];
  unsigned char* hi = g_QA + (size_t)bc*163840 + (size_t)row*80;
  unsigned char* lo = hi + 81920;
  float x[8]; uint4 h, l;
  #pragma unroll
  for (int g = 0; g < 4; g++) {
    *(float4*)&x[0] = *(const float4*)(src + g*8);
    *(float4*)&x[4] = *(const float4*)(src + g*8 + 4);
    cvt8(x, &h, &l);
    *(uint4*)(hi + g*16) = h;
    *(uint4*)(lo + g*16) = l;
  }
}
__global__ __launch_bounds__(256) void convKV_kernel(const float* __restrict__ srcB,
                                                    unsigned char* __restrict__ dstB)
{
  int bc = blockIdx.x / 7, rp = blockIdx.x % 7;
  int row = rp*256 + threadIdx.x;        // 0..1791
  int kt = row >> 7, rloc = row & 127;
  bool ok = row < KTOK;
  const float* src = &srcB[((size_t)bc*KTOK + (ok ? row : 0))*DH];
  unsigned char* hi = dstB + ((size_t)bc*TPC + kt)*20480 + (size_t)rloc*80;
  unsigned char* lo = hi + 10240;
  float x[8]; uint4 h, l;
  #pragma unroll
  for (int g = 0; g < 4; g++) {
    if (ok) {
      *(float4*)&x[0] = *(const float4*)(src + g*8);
      *(float4*)&x[4] = *(const float4*)(src + g*8 + 4);
    } else {
      #pragma unroll
      for (int j = 0; j < 8; j++) x[j] = 0.f;
    }
    cvt8(x, &h, &l);
    *(uint4*)(hi + g*16) = h;
    *(uint4*)(lo + g*16) = l;
  }
}

// ---------- mma.sync bf16 attention ----------
// grid NB*NH*16 (64-q tiles), 256 thr: warp = qw(0-3) x kh(0-1)
#define KOFF 61440
#define VOFF 81920
#define ATTN_SMEM 102400

__global__ void __launch_bounds__(256, 2) attn_mma_kernel()
{
  extern __shared__ __align__(16) unsigned char smem[];
  const int tid = threadIdx.x;
  const int wid = tid >> 5, lane = tid & 31;
  const int qw = wid & 3, kh = wid >> 2;
  const int koff = kh * 64;
  const int bh = blockIdx.x >> 4, qt = blockIdx.x & 15;
  const int b = bh >> 2, h = bh & 3;
  const u32 sb = smem_u32(smem);

  // stage Q (61440B)
  {
    const size_t bc0 = (size_t)bh * NCAM;
    for (int i = tid; i < 3840; i += 256) {
      int cam = i / 640, r2 = i % 640;
      int pl = r2 / 320, w16 = r2 % 320;
      const uint4* src = (const uint4*)(g_QA + (bc0 + cam)*163840 + (size_t)pl*81920
                                        + (size_t)qt*5120 + (size_t)w16*16);
      *(uint4*)(smem + cam*10240 + pl*5120 + w16*16) = *src;
    }
  }

  float S[8][4];
  float O[4][4];
  float l0 = 0.f, l1 = 0.f;
  u32 QHI[2][4], QLO[2][4];
  #pragma unroll
  for (int dt = 0; dt < 4; dt++)
    #pragma unroll
    for (int i = 0; i < 4; i++) O[dt][i] = 0.f;

  const int arow = (lane & 7) + ((lane >> 3) & 1) * 8;
  const int abyte = ((lane >> 4) & 1) * 16;
  const int krow = lane & 7;
  const int kbyte = (lane >> 3) * 16;

  for (int t = 0; t < NTT; ++t) {
    const int cam = t / TPC, kt = t - cam*TPC;
    __syncthreads();
    // stage K+V (40960B)
    {
      const uint4* ks = (const uint4*)(g_KB + ((size_t)(bh*NCAM + cam)*TPC + kt)*20480);
      const uint4* vs = (const uint4*)(g_VB + ((size_t)(bh*NCAM + cam)*TPC + kt)*20480);
      for (int i = tid; i < 2560; i += 256) {
        if (i < 1280) *(uint4*)(smem + KOFF + i*16) = ks[i];
        else          *(uint4*)(smem + VOFF + (i-1280)*16) = vs[i-1280];
      }
    }
    __syncthreads();

    if (kt == 0) {   // Q fragments for this camera
      u32 qb = sb + cam*10240 + (qw*16 + arow)*80 + abyte;
      #pragma unroll
      for (int c = 0; c < 2; c++) {
        ldsm4(qb + c*32,        QHI[c][0], QHI[c][1], QHI[c][2], QHI[c][3]);
        ldsm4(qb + 5120 + c*32, QLO[c][0], QLO[c][1], QLO[c][2], QLO[c][3]);
      }
    }

    // ---- QK logits ----
    #pragma unroll
    for (int j = 0; j < 8; j++)
      #pragma unroll
      for (int i = 0; i < 4; i++) S[j][i] = 0.f;
    #pragma unroll
    for (int j = 0; j < 8; j++) {
      u32 kb = sb + KOFF + (koff + j*8 + krow)*80 + kbyte;
      u32 kh0,kh1,kh2,kh3, kl0,kl1,kl2,kl3;
      ldsm4(kb,         kh0,kh1,kh2,kh3);
      ldsm4(kb + 10240, kl0,kl1,kl2,kl3);
      mma16816(S[j], QHI[0][0],QHI[0][1],QHI[0][2],QHI[0][3], kh0,kh1);
      mma16816(S[j], QHI[1][0],QHI[1][1],QHI[1][2],QHI[1][3], kh2,kh3);
      mma16816(S[j], QLO[0][0],QLO[0][1],QLO[0][2],QLO[0][3], kh0,kh1);
      mma16816(S[j], QLO[1][0],QLO[1][1],QLO[1][2],QLO[1][3], kh2,kh3);
      mma16816(S[j], QHI[0][0],QHI[0][1],QHI[0][2],QHI[0][3], kl0,kl1);
      mma16816(S[j], QHI[1][0],QHI[1][1],QHI[1][2],QHI[1][3], kl2,kl3);
    }

    // ---- softmax + PV per 16-key chunk ----
    #pragma unroll
    for (int c = 0; c < 4; ++c) {
      const int j0 = 2*c, j1 = j0 + 1;
      const bool vt0 = (kt != TPC-1) || (kh == 0 && j0 < 2);
      const bool vt1 = (kt != TPC-1) || (kh == 0 && j1 < 2);
      if (!vt0 && !vt1) continue;
      float p[8];
      p[0] = vt0 ? __expf(S[j0][0]) : 0.f;
      p[1] = vt0 ? __expf(S[j0][1]) : 0.f;
      p[2] = vt0 ? __expf(S[j0][2]) : 0.f;
      p[3] = vt0 ? __expf(S[j0][3]) : 0.f;
      p[4] = vt1 ? __expf(S[j1][0]) : 0.f;
      p[5] = vt1 ? __expf(S[j1][1]) : 0.f;
      p[6] = vt1 ? __expf(S[j1][2]) : 0.f;
      p[7] = vt1 ? __expf(S[j1][3]) : 0.f;
      l0 += p[0] + p[1] + p[4] + p[5];
      l1 += p[2] + p[3] + p[6] + p[7];
      u32 PHI[4], PLO[4];
      #pragma unroll
      for (int g = 0; g < 4; g++) {
        float a = p[2*g], bb = p[2*g+1];
        u32 hp = pkbf(a, bb);
        PHI[g] = hp;
        PLO[g] = pkbf(a - __uint_as_float(hp << 16),
                      bb - __uint_as_float(hp & 0xffff0000u));
      }
      u32 vbase = sb + VOFF + (koff + c*16 + arow)*80 + ((lane >> 4) & 1)*16;
      #pragma unroll
      for (int db = 0; db < 2; db++) {
        u32 vh0,vh1,vh2,vh3, vl0,vl1,vl2,vl3;
        ldsm4t(vbase + db*32,         vh0,vh1,vh2,vh3);
        ldsm4t(vbase + 10240 + db*32, vl0,vl1,vl2,vl3);
        mma16816(O[db*2],   PHI[0],PHI[1],PHI[2],PHI[3], vh0,vh1);
        mma16816(O[db*2+1], PHI[0],PHI[1],PHI[2],PHI[3], vh2,vh3);
        mma16816(O[db*2],   PLO[0],PLO[1],PLO[2],PLO[3], vh0,vh1);
        mma16816(O[db*2+1], PLO[0],PLO[1],PLO[2],PLO[3], vh2,vh3);
        mma16816(O[db*2],   PHI[0],PHI[1],PHI[2],PHI[3], vl0,vl1);
        mma16816(O[db*2+1], PHI[0],PHI[1],PHI[2],PHI[3], vl2,vl3);
      }
    }
  }

  // ---- reduce l across row quads ----
  l0 += __shfl_xor_sync(0xffffffffu, l0, 1);
  l0 += __shfl_xor_sync(0xffffffffu, l0, 2);
  l1 += __shfl_xor_sync(0xffffffffu, l1, 1);
  l1 += __shfl_xor_sync(0xffffffffu, l1, 2);

  __syncthreads();   // done with K/V/Q smem
  float* Os = (float*)smem;            // [2][64][32]
  float* ls = (float*)(smem + 16384);  // [2][64]
  {
    int r0 = qw*16 + (lane >> 2), c0 = 2*(lane & 3);
    #pragma unroll
    for (int dt = 0; dt < 4; dt++) {
      Os[(kh*64 + r0)*32 + dt*8 + c0]     = O[dt][0];
      Os[(kh*64 + r0)*32 + dt*8 + c0 + 1] = O[dt][1];
      Os[(kh*64 + r0 + 8)*32 + dt*8 + c0]     = O[dt][2];
      Os[(kh*64 + r0 + 8)*32 + dt*8 + c0 + 1] = O[dt][3];
    }
    if ((lane & 3) == 0) { ls[kh*64 + r0] = l0; ls[kh*64 + r0 + 8] = l1; }
  }
  __syncthreads();
  for (int i = tid; i < 2048; i += 256) {
    int q = i >> 5, d = i & 31;
    float val = (Os[q*32 + d] + Os[(64 + q)*32 + d]) / (ls[q] + ls[64 + q]);
    g_A[((size_t)b*QTOK + qt*64 + q)*DIM + h*DH + d] = val;
  }
}

// ---------- out-proj + skip + pre-LN ----------
__global__ __launch_bounds__(256) void aproj_kernel(
    const float* __restrict__ skip, const float* __restrict__ Wp,
    const float* __restrict__ bp, const float* __restrict__ pg,
    const float* __restrict__ pb)
{
  extern __shared__ float sm[];
  float* xs = sm;
  float* mu = xs + 8192; float* rs = mu + 64;
  float* Ws = rs + 64;
  const int tid = threadIdx.x;
  const int tok0 = blockIdx.x * 64;
  const int b = tok0 >> 10, qb0 = tok0 & 1023;

  for (int idx = tid; idx < 8192; idx += 256) {
    int t = idx >> 7, d = idx & 127;
    xs[d*64 + t] = g_A[(size_t)(tok0 + t)*DIM + d];
  }
  for (int idx = tid; idx < DIM*DIM; idx += 256) Ws[idx] = Wp[idx];
  __syncthreads();

  const int tk = tid & 15, jg = tid >> 4;
  float acc[4][8];
  #pragma unroll
  for (int i = 0; i < 4; i++)
    #pragma unroll
    for (int jj = 0; jj < 8; jj++) acc[i][jj] = bp[jg*8 + jj];
  #pragma unroll 4
  for (int d = 0; d < DIM; d++) {
    float xv[4];
    #pragma unroll
    for (int i = 0; i < 4; i++) xv[i] = xs[d*64 + tk*4 + i];
    const float* wr = Ws + d*DIM + jg*8;
    #pragma unroll
    for (int jj = 0; jj < 8; jj++) {
      float w = wr[jj];
      #pragma unroll
      for (int i = 0; i < 4; i++) acc[i][jj] += xv[i] * w;
    }
  }
  #pragma unroll
  for (int i = 0; i < 4; i++)
    #pragma unroll
    for (int jj = 0; jj < 8; jj++)
      acc[i][jj] += skip[((size_t)b*DIM + jg*8 + jj)*QTOK + qb0 + tk*4 + i];
  __syncthreads();
  #pragma unroll
  for (int i = 0; i < 4; i++)
    #pragma unroll
    for (int jj = 0; jj < 8; jj++)
      xs[(jg*8 + jj)*64 + tk*4 + i] = acc[i][jj];
  __syncthreads();
  if (tid < 64) {
    float s = 0.f, s2 = 0.f;
    #pragma unroll 8
    for (int j = 0; j < DIM; j++) { float v = xs[j*64 + tid]; s += v; s2 += v*v; }
    float mval = s * (1.f/DIM);
    float var = fmaxf(s2 * (1.f/DIM) - mval*mval, 0.f);
    mu[tid] = mval; rs[tid] = rsqrtf(var + 1e-5f);
  }
  __syncthreads();
  for (int idx = tid; idx < 8192; idx += 256) {
    int t = idx >> 7, d = idx & 127;
    g_Z[(size_t)(tok0 + t)*DIM + d] = (xs[d*64 + t] - mu[t]) * rs[t] * pg[d] + pb[d];
  }
}

// ---------- MLP1 ----------
__global__ __launch_bounds__(256) void mlp1_kernel(
    const float* __restrict__ W1, const float* __restrict__ b1)
{
  extern __shared__ float sm[];
  float* xs = sm;
  float* Ws = xs + 8192;
  const int tid = threadIdx.x;
  const int tok0 = blockIdx.x * 64;

  for (int idx = tid; idx < 8192; idx += 256) {
    int t = idx >> 7, d = idx & 127;
    xs[d*64 + t] = g_Z[(size_t)(tok0 + t)*DIM + d];
  }
  for (int idx = tid; idx < DIM*2*DIM; idx += 256) Ws[idx] = W1[idx];
  __syncthreads();

  const int tk = tid & 15, jg = tid >> 4;
  float acc[4][16];
  #pragma unroll
  for (int i = 0; i < 4; i++)
    #pragma unroll
    for (int jj = 0; jj < 16; jj++) acc[i][jj] = b1[jg*16 + jj];
  #pragma unroll 2
  for (int d = 0; d < DIM; d++) {
    float xv[4];
    #pragma unroll
    for (int i = 0; i < 4; i++) xv[i] = xs[d*64 + tk*4 + i];
    const float* wr = Ws + d*2*DIM + jg*16;
    #pragma unroll
    for (int jj = 0; jj < 16; jj++) {
      float w = wr[jj];
      #pragma unroll
      for (int i = 0; i < 4; i++) acc[i][jj] += xv[i] * w;
    }
  }
  #pragma unroll
  for (int i = 0; i < 4; i++) {
    int t = tk*4 + i;
    #pragma unroll
    for (int jj = 0; jj < 16; jj++) {
      float x = acc[i][jj];
      g_Hb[(size_t)(tok0 + t)*(2*DIM) + jg*16 + jj] =
          0.5f * x * (1.f + erff(x * 0.70710678118654752f));
    }
  }
}

// ---------- MLP2 + residual + post-LN + transpose ----------
__global__ __launch_bounds__(256) void mlp2_kernel(
    const float* __restrict__ W2, const float* __restrict__ b2,
    const float* __restrict__ pg, const float* __restrict__ pb,
    float* __restrict__ out)
{
  extern __shared__ float sm[];
  float* xs = sm;
  float* mu = xs + 16384; float* rs = mu + 64;
  float* Ws = rs + 64;
  const int tid = threadIdx.x;
  const int tok0 = blockIdx.x * 64;
  const int b = tok0 >> 10, qb0 = tok0 & 1023;

  for (int idx = tid; idx < 16384; idx += 256) {
    int t = idx >> 8, d = idx & 255;
    xs[d*64 + t] = g_Hb[(size_t)(tok0 + t)*(2*DIM) + d];
  }
  for (int idx = tid; idx < 2*DIM*DIM; idx += 256) Ws[idx] = W2[idx];
  __syncthreads();

  const int tk = tid & 15, jg = tid >> 4;
  float acc[4][8];
  #pragma unroll
  for (int i = 0; i < 4; i++)
    #pragma unroll
    for (int jj = 0; jj < 8; jj++) acc[i][jj] = b2[jg*8 + jj];
  #pragma unroll 4
  for (int d = 0; d < 2*DIM; d++) {
    float xv[4];
    #pragma unroll
    for (int i = 0; i < 4; i++) xv[i] = xs[d*64 + tk*4 + i];
    const float* wr = Ws + d*DIM + jg*8;
    #pragma unroll
    for (int jj = 0; jj < 8; jj++) {
      float w = wr[jj];
      #pragma unroll
      for (int i = 0; i < 4; i++) acc[i][jj] += xv[i] * w;
    }
  }
  #pragma unroll
  for (int i = 0; i < 4; i++)
    #pragma unroll
    for (int jj = 0; jj < 8; jj++)
      acc[i][jj] += g_Z[(size_t)(tok0 + tk*4 + i)*DIM + jg*8 + jj];
  __syncthreads();
  #pragma unroll
  for (int i = 0; i < 4; i++)
    #pragma unroll
    for (int jj = 0; jj < 8; jj++)
      xs[(jg*8 + jj)*64 + tk*4 + i] = acc[i][jj];
  __syncthreads();
  if (tid < 64) {
    float s = 0.f, s2 = 0.f;
    #pragma unroll 8
    for (int j = 0; j < DIM; j++) { float v = xs[j*64 + tid]; s += v; s2 += v*v; }
    float mval = s * (1.f/DIM);
    float var = fmaxf(s2 * (1.f/DIM) - mval*mval, 0.f);
    mu[tid] = mval; rs[tid] = rsqrtf(var + 1e-5f);
  }
  __syncthreads();
  for (int idx = tid; idx < 8192; idx += 256) {
    int d = idx >> 6, t = idx & 63;
    out[((size_t)b*DIM + d)*QTOK + qb0 + t] =
        (xs[d*64 + t] - mu[t]) * rs[t] * pg[d] + pb[d];
  }
}

// ---------- host launcher ----------
extern "C" void kernel_launch(void* const* d_in, const int* in_sizes, int n_in,
                              void* d_out, int out_size)
{
  const float* q      = (const float*)d_in[0];
  const float* k      = (const float*)d_in[1];
  const float* v      = (const float*)d_in[2];
  const float* skip   = (const float*)d_in[3];
  const float* q_ln_g = (const float*)d_in[4];
  const float* q_ln_b = (const float*)d_in[5];
  const float* Wq     = (const float*)d_in[6];
  const float* bq     = (const float*)d_in[7];
  const float* k_ln_g = (const float*)d_in[8];
  const float* k_ln_b = (const float*)d_in[9];
  const float* Wk     = (const float*)d_in[10];
  const float* bk     = (const float*)d_in[11];
  const float* v_ln_g = (const float*)d_in[12];
  const float* v_ln_b = (const float*)d_in[13];
  const float* Wv     = (const float*)d_in[14];
  const float* bv     = (const float*)d_in[15];
  const float* Wp     = (const float*)d_in[16];
  const float* bp     = (const float*)d_in[17];
  const float* pre_g  = (const float*)d_in[18];
  const float* pre_b  = (const float*)d_in[19];
  const float* W1     = (const float*)d_in[20];
  const float* b1     = (const float*)d_in[21];
  const float* W2     = (const float*)d_in[22];
  const float* b2     = (const float*)d_in[23];
  const float* post_g = (const float*)d_in[24];
  const float* post_b = (const float*)d_in[25];
  float* out = (float*)d_out;

  float *dQh, *dKh, *dVh;
  unsigned char *dKB, *dVB;
  cudaGetSymbolAddress((void**)&dQh, g_Qh);
  cudaGetSymbolAddress((void**)&dKh, g_Kh);
  cudaGetSymbolAddress((void**)&dVh, g_Vh);
  cudaGetSymbolAddress((void**)&dKB, g_KB);
  cudaGetSymbolAddress((void**)&dVB, g_VB);

  const int projSm = (8192 + 128 + 16384) * 4;
  const int mlp1Sm = (8192 + 32768) * 4;
  const int mlp2Sm = (16384 + 128 + 32768) * 4;

  static bool attrSet = false;
  if (!attrSet) {
    cudaFuncSetAttribute(proj_kernel,     cudaFuncAttributeMaxDynamicSharedMemorySize, projSm);
    cudaFuncSetAttribute(attn_mma_kernel, cudaFuncAttributeMaxDynamicSharedMemorySize, ATTN_SMEM);
    cudaFuncSetAttribute(aproj_kernel,    cudaFuncAttributeMaxDynamicSharedMemorySize, projSm);
    cudaFuncSetAttribute(mlp1_kernel,     cudaFuncAttributeMaxDynamicSharedMemorySize, mlp1Sm);
    cudaFuncSetAttribute(mlp2_kernel,     cudaFuncAttributeMaxDynamicSharedMemorySize, mlp2Sm);
    attrSet = true;
  }

  const float qscale = rsqrtf((float)DH);
  proj_kernel<<<NB*NCAM*16, 256, projSm>>>(q, q_ln_g, q_ln_b, Wq, bq, dQh, QTOK, 16, qscale);
  proj_kernel<<<NB*NCAM*27, 256, projSm>>>(k, k_ln_g, k_ln_b, Wk, bk, dKh, KTOK, 27, 1.f);
  proj_kernel<<<NB*NCAM*27, 256, projSm>>>(v, v_ln_g, v_ln_b, Wv, bv, dVh, KTOK, 27, 1.f);
  convQ_kernel<<<NB*NH*NCAM*4, 256>>>();
  convKV_kernel<<<NB*NH*NCAM*7, 256>>>(dKh, dKB);
  convKV_kernel<<<NB*NH*NCAM*7, 256>>>(dVh, dVB);
  attn_mma_kernel<<<NB*NH*16, 256, ATTN_SMEM>>>();
  aproj_kernel<<<NB*QTOK/64, 256, projSm>>>(skip, Wp, bp, pre_g, pre_b);
  mlp1_kernel<<<NB*QTOK/64, 256, mlp1Sm>>>(W1, b1);
  mlp2_kernel<<<NB*QTOK/64, 256, mlp2Sm>>>(W2, b2, post_g, post_b, out);
  (void)in_sizes; (void)n_in; (void)out_size;
}